// round 10
// baseline (speedup 1.0000x reference)
#include <cuda_runtime.h>
#include <cuda_bf16.h>
#include <mma.h>
#include <cstdint>

using namespace nvcuda;

#define N_NODES 50000
#define N_EDGES 800000
#define EDGE_DIM 16
#define EMB 128
#define HID 256

#define SCAN_BLK 256
#define SCAN_ITEMS 4
#define SCAN_TILE (SCAN_BLK * SCAN_ITEMS)            // 1024
#define SCAN_NBLK ((N_NODES + SCAN_TILE - 1) / SCAN_TILE)  // 49

typedef __nv_bfloat16 bf16;
typedef __nv_bfloat162 bf162;

// ------------------------- scratch (static device arrays; no allocs) -------
__device__ int   g_cnt[N_NODES];
__device__ int   g_part[SCAN_NBLK];
__device__ int   g_rowptr[N_NODES + 1];
__device__ int   g_cursor[N_NODES];
__device__ int   g_csr_src[N_EDGES];
__device__ int   g_csr_eid[N_EDGES];
__device__ bf16  g_a_hi[(size_t)N_NODES * EMB];
__device__ bf16  g_a_lo[(size_t)N_NODES * EMB];
__device__ bf16  g_c1_hi[(size_t)N_NODES * HID];
__device__ bf16  g_c1_lo[(size_t)N_NODES * HID];
__device__ bf16  g_w1_hi[EMB * HID], g_w1_lo[EMB * HID];
__device__ bf16  g_w2_hi[HID * EMB], g_w2_lo[HID * EMB];
__device__ float g_h[(size_t)N_NODES * EMB];
__device__ float g_sum[EMB];
__device__ float g_sumsq[EMB];
__device__ float g_scale[EMB];
__device__ float g_shift[EMB];

// ------------------------- helpers -----------------------------------------
__device__ __forceinline__ uint32_t smem_u32(const void* p) {
  uint32_t a;
  asm("{ .reg .u64 t; cvta.to.shared.u64 t, %1; cvt.u32.u64 %0, t; }" : "=r"(a) : "l"(p));
  return a;
}
__device__ __forceinline__ void cp16(uint32_t dst, const void* src) {
  asm volatile("cp.async.cg.shared.global [%0], [%1], 16;" :: "r"(dst), "l"(src));
}
__device__ __forceinline__ void cp16z(uint32_t dst, const void* src, uint32_t srcsz) {
  asm volatile("cp.async.cg.shared.global [%0], [%1], 16, %2;"
               :: "r"(dst), "l"(src), "r"(srcsz));
}
#define CP_COMMIT() asm volatile("cp.async.commit_group;" ::: "memory")
#define CP_WAIT1()  asm volatile("cp.async.wait_group 1;" ::: "memory")

__device__ __forceinline__ void splitbf(float x, bf16& hi, bf16& lo) {
  hi = __float2bfloat16(x);
  lo = __float2bfloat16(x - __bfloat162float(hi));
}

// ------------------------- zero scratch ------------------------------------
__global__ void zero_kernel() {
  int i = blockIdx.x * blockDim.x + threadIdx.x;
  if (i < N_NODES) g_cnt[i] = 0;
  if (i < EMB) { g_sum[i] = 0.f; g_sumsq[i] = 0.f; }
}

// ------------------------- split weights ------------------------------------
__global__ void split_weights(const float* __restrict__ W1, const float* __restrict__ W2) {
  int i = blockIdx.x * blockDim.x + threadIdx.x;
  if (i < EMB * HID) {
    splitbf(W1[i], g_w1_hi[i], g_w1_lo[i]);
    splitbf(W2[i], g_w2_hi[i], g_w2_lo[i]);
  }
}

// ------------------------- CSR build ----------------------------------------
__global__ void hist_kernel(const int* __restrict__ dst) {
  int e = blockIdx.x * blockDim.x + threadIdx.x;
  if (e < N_EDGES) atomicAdd(&g_cnt[dst[e]], 1);
}

__global__ __launch_bounds__(SCAN_BLK)
void scan_phase1() {
  __shared__ int wsum[SCAN_BLK / 32];
  int tid = threadIdx.x;
  int base = blockIdx.x * SCAN_TILE + tid * SCAN_ITEMS;
  int s = 0;
#pragma unroll
  for (int j = 0; j < SCAN_ITEMS; j++) {
    int i = base + j;
    if (i < N_NODES) s += g_cnt[i];
  }
#pragma unroll
  for (int o = 16; o > 0; o >>= 1) s += __shfl_down_sync(0xffffffffu, s, o);
  if ((tid & 31) == 0) wsum[tid >> 5] = s;
  __syncthreads();
  if (tid == 0) {
    int t = 0;
#pragma unroll
    for (int w = 0; w < SCAN_BLK / 32; w++) t += wsum[w];
    g_part[blockIdx.x] = t;
  }
}

__global__ void scan_phase2() {
  if (threadIdx.x == 0) {
    int run = 0;
    for (int i = 0; i < SCAN_NBLK; i++) { int v = g_part[i]; g_part[i] = run; run += v; }
    g_rowptr[N_NODES] = run;
  }
}

__global__ __launch_bounds__(SCAN_BLK)
void scan_phase3() {
  __shared__ int wsum[SCAN_BLK / 32];
  int tid = threadIdx.x;
  int lane = tid & 31, w = tid >> 5;
  int base = blockIdx.x * SCAN_TILE + tid * SCAN_ITEMS;
  int v[SCAN_ITEMS];
  int s = 0;
#pragma unroll
  for (int j = 0; j < SCAN_ITEMS; j++) {
    int i = base + j;
    v[j] = (i < N_NODES) ? g_cnt[i] : 0;
    s += v[j];
  }
  int inc = s;
#pragma unroll
  for (int o = 1; o < 32; o <<= 1) {
    int t = __shfl_up_sync(0xffffffffu, inc, o);
    if (lane >= o) inc += t;
  }
  if (lane == 31) wsum[w] = inc;
  __syncthreads();
  if (w == 0) {
    int ws = (lane < SCAN_BLK / 32) ? wsum[lane] : 0;
#pragma unroll
    for (int o = 1; o < SCAN_BLK / 32; o <<= 1) {
      int t = __shfl_up_sync(0xffffffffu, ws, o);
      if (lane >= o) ws += t;
    }
    if (lane < SCAN_BLK / 32) wsum[lane] = ws;
  }
  __syncthreads();
  int excl = inc - s + (w > 0 ? wsum[w - 1] : 0) + g_part[blockIdx.x];
#pragma unroll
  for (int j = 0; j < SCAN_ITEMS; j++) {
    int i = base + j;
    if (i < N_NODES) { g_rowptr[i] = excl; g_cursor[i] = excl; }
    excl += v[j];
  }
}

__global__ void scatter_kernel(const int* __restrict__ src, const int* __restrict__ dst) {
  int e = blockIdx.x * blockDim.x + threadIdx.x;
  if (e >= N_EDGES) return;
  int pos = atomicAdd(&g_cursor[dst[e]], 1);
  g_csr_src[pos] = src[e];
  g_csr_eid[pos] = e;
}

// ------------------------- gather-aggregate + combine (fused) ----------------
__global__ __launch_bounds__(256)
void aggregate_kernel(const float* __restrict__ nf, const float* __restrict__ ef,
                      const float* __restrict__ W_edge, const float* __restrict__ b_edge) {
  __shared__ float sW[EDGE_DIM][EMB];
  __shared__ float sbe[EMB];
  int tid = threadIdx.x;
  for (int i = tid; i < EDGE_DIM * EMB; i += 256) sW[i >> 7][i & 127] = W_edge[i];
  if (tid < EMB) sbe[tid] = b_edge[tid];
  __syncthreads();

  int w = tid >> 5, lane = tid & 31;
  int n = blockIdx.x * 8 + w;
  if (n >= N_NODES) return;
  int beg = g_rowptr[n], endp = g_rowptr[n + 1];
  float deg = (float)(endp - beg);

  const float4* nf4 = reinterpret_cast<const float4*>(nf);
  const float4* ef4 = reinterpret_cast<const float4*>(ef);

  float4 acc0 = make_float4(0.f, 0.f, 0.f, 0.f);
  float4 acc1 = make_float4(0.f, 0.f, 0.f, 0.f);
  float4 ea0 = make_float4(0.f, 0.f, 0.f, 0.f);
  float4 ea1 = make_float4(0.f, 0.f, 0.f, 0.f);

  int i = beg;
  for (; i + 1 < endp; i += 2) {
    int s0 = g_csr_src[i], s1 = g_csr_src[i + 1];
    float4 v0 = __ldg(&nf4[(size_t)s0 * 32 + lane]);
    float4 v1 = __ldg(&nf4[(size_t)s1 * 32 + lane]);
    acc0.x += v0.x; acc0.y += v0.y; acc0.z += v0.z; acc0.w += v0.w;
    acc1.x += v1.x; acc1.y += v1.y; acc1.z += v1.z; acc1.w += v1.w;
    if (lane < 4) {
      int e0 = g_csr_eid[i], e1 = g_csr_eid[i + 1];
      float4 t0 = __ldg(&ef4[(size_t)e0 * 4 + lane]);
      float4 t1 = __ldg(&ef4[(size_t)e1 * 4 + lane]);
      ea0.x += t0.x; ea0.y += t0.y; ea0.z += t0.z; ea0.w += t0.w;
      ea1.x += t1.x; ea1.y += t1.y; ea1.z += t1.z; ea1.w += t1.w;
    }
  }
  if (i < endp) {
    int s0 = g_csr_src[i];
    float4 v0 = __ldg(&nf4[(size_t)s0 * 32 + lane]);
    acc0.x += v0.x; acc0.y += v0.y; acc0.z += v0.z; acc0.w += v0.w;
    if (lane < 4) {
      int e0 = g_csr_eid[i];
      float4 t0 = __ldg(&ef4[(size_t)e0 * 4 + lane]);
      ea0.x += t0.x; ea0.y += t0.y; ea0.z += t0.z; ea0.w += t0.w;
    }
  }
  float4 acc = make_float4(acc0.x + acc1.x, acc0.y + acc1.y,
                           acc0.z + acc1.z, acc0.w + acc1.w);
  float4 ea = make_float4(ea0.x + ea1.x, ea0.y + ea1.y, ea0.z + ea1.z, ea0.w + ea1.w);

  int srcl = lane >> 2, comp = lane & 3;
  float ex = __shfl_sync(0xffffffffu, ea.x, srcl);
  float ey = __shfl_sync(0xffffffffu, ea.y, srcl);
  float ez = __shfl_sync(0xffffffffu, ea.z, srcl);
  float ew = __shfl_sync(0xffffffffu, ea.w, srcl);
  float ev = (comp == 0) ? ex : (comp == 1) ? ey : (comp == 2) ? ez : ew;

  int c4 = lane * 4;
  acc.x += deg * sbe[c4 + 0];
  acc.y += deg * sbe[c4 + 1];
  acc.z += deg * sbe[c4 + 2];
  acc.w += deg * sbe[c4 + 3];
#pragma unroll
  for (int k = 0; k < EDGE_DIM; k++) {
    float s = __shfl_sync(0xffffffffu, ev, k);
    acc.x = fmaf(s, sW[k][c4 + 0], acc.x);
    acc.y = fmaf(s, sW[k][c4 + 1], acc.y);
    acc.z = fmaf(s, sW[k][c4 + 2], acc.z);
    acc.w = fmaf(s, sW[k][c4 + 3], acc.w);
  }
  bf162 h0, h1, l0, l1;
  splitbf(acc.x, h0.x, l0.x); splitbf(acc.y, h0.y, l0.y);
  splitbf(acc.z, h1.x, l1.x); splitbf(acc.w, h1.y, l1.y);
  size_t off = (size_t)n * EMB + c4;
  *reinterpret_cast<bf162*>(&g_a_hi[off]) = h0;
  *reinterpret_cast<bf162*>(&g_a_hi[off + 2]) = h1;
  *reinterpret_cast<bf162*>(&g_a_lo[off]) = l0;
  *reinterpret_cast<bf162*>(&g_a_lo[off + 2]) = l1;
}

// ------------------------- pipelined bf16 wmma GEMM -------------------------
// Tight strides (conflict-free: 80B rows -> bank=(20r)%32 distinct; 272B rows
// -> bank=(68r)%32=4r distinct) shrink a stage to 37,888B so the double
// buffer fits 3 CTAs/SM (75,776B each).
#define A_STRIDE 40
#define B_STRIDE 136
#define A_HI_OFF 0
#define A_LO_OFF (128 * A_STRIDE)                     // 5120
#define B_HI_OFF (2 * 128 * A_STRIDE)                 // 10240
#define B_LO_OFF (B_HI_OFF + 32 * B_STRIDE)           // 14592
#define STAGE_ELEMS (B_LO_OFF + 32 * B_STRIDE)        // 18944
#define STAGE_BYTES (STAGE_ELEMS * 2)                 // 37888
#define GEMM_SMEM_BYTES (2 * STAGE_BYTES)             // 75776
#define EPI_STRIDE 132

template <int N_, int K_, bool FIRST>
__global__ __launch_bounds__(256, 3)
void wmma_gemm(const float* __restrict__ bias) {
  constexpr int M = N_NODES;
  constexpr int CH = K_ / 32;
  const bf16* __restrict__ Ahi = FIRST ? g_a_hi : g_c1_hi;
  const bf16* __restrict__ Alo = FIRST ? g_a_lo : g_c1_lo;
  const bf16* __restrict__ Whi = FIRST ? g_w1_hi : g_w2_hi;
  const bf16* __restrict__ Wlo = FIRST ? g_w1_lo : g_w2_lo;

  extern __shared__ __align__(16) bf16 smb[];
  float* smf = reinterpret_cast<float*>(smb);
  __shared__ float sbias[128];
  const uint32_t smb_b = smem_u32(smb);

  int tid = threadIdx.x;
  int wid = tid >> 5;
  int wm = wid & 3;
  int wn = wid >> 2;
  int bm = blockIdx.y * 128;
  int bn = blockIdx.x * 128;

  if (tid < 128) sbias[tid] = bias[bn + tid];

  wmma::fragment<wmma::accumulator, 16, 16, 16, float> acc[2][4];
#pragma unroll
  for (int mt = 0; mt < 2; mt++)
#pragma unroll
    for (int nt = 0; nt < 4; nt++) wmma::fill_fragment(acc[mt][nt], 0.f);

  auto prefetch = [&](int c, int s) {
    uint32_t base = smb_b + (uint32_t)s * STAGE_BYTES;
    int k0 = c * 32;
#pragma unroll
    for (int l = 0; l < 2; l++) {
      int u = tid + l * 256;
      int ar = u >> 2, as = u & 3;
      int gr = bm + ar;
      uint32_t ok = (gr < M) ? 16u : 0u;
      size_t ago = (size_t)gr * K_ + k0 + as * 8;
      uint32_t aso = (uint32_t)(ar * A_STRIDE + as * 8) * 2;
      cp16z(base + A_HI_OFF * 2 + aso, &Ahi[ago], ok);
      cp16z(base + A_LO_OFF * 2 + aso, &Alo[ago], ok);
      int br = u >> 4, bs = u & 15;
      size_t bgo = (size_t)(k0 + br) * N_ + bn + bs * 8;
      uint32_t bso = (uint32_t)(br * B_STRIDE + bs * 8) * 2;
      cp16(base + B_HI_OFF * 2 + bso, &Whi[bgo]);
      cp16(base + B_LO_OFF * 2 + bso, &Wlo[bgo]);
    }
  };

  prefetch(0, 0); CP_COMMIT();
  prefetch(1, 1); CP_COMMIT();

  for (int c = 0; c < CH; c++) {
    CP_WAIT1();
    __syncthreads();
    const bf16* st = smb + (c & 1) * STAGE_ELEMS;
#pragma unroll
    for (int ks = 0; ks < 2; ks++) {
      wmma::fragment<wmma::matrix_a, 16, 16, 16, bf16, wmma::row_major> ah[2], al[2];
#pragma unroll
      for (int mt = 0; mt < 2; mt++) {
        const bf16* ap = st + (wm * 32 + mt * 16) * A_STRIDE + ks * 16;
        wmma::load_matrix_sync(ah[mt], ap + A_HI_OFF, A_STRIDE);
        wmma::load_matrix_sync(al[mt], ap + A_LO_OFF, A_STRIDE);
      }
#pragma unroll
      for (int nt = 0; nt < 4; nt++) {
        wmma::fragment<wmma::matrix_b, 16, 16, 16, bf16, wmma::row_major> bh, bl;
        const bf16* bp = st + (ks * 16) * B_STRIDE + wn * 64 + nt * 16;
        wmma::load_matrix_sync(bh, bp + B_HI_OFF, B_STRIDE);
        wmma::load_matrix_sync(bl, bp + B_LO_OFF, B_STRIDE);
#pragma unroll
        for (int mt = 0; mt < 2; mt++) {
          wmma::mma_sync(acc[mt][nt], ah[mt], bh, acc[mt][nt]);
          wmma::mma_sync(acc[mt][nt], al[mt], bh, acc[mt][nt]);
          wmma::mma_sync(acc[mt][nt], ah[mt], bl, acc[mt][nt]);
        }
      }
    }
    __syncthreads();
    if (c + 2 < CH) prefetch(c + 2, c & 1);
    CP_COMMIT();
  }

#pragma unroll
  for (int mt = 0; mt < 2; mt++)
#pragma unroll
    for (int nt = 0; nt < 4; nt++)
      wmma::store_matrix_sync(&smf[(wm * 32 + mt * 16) * EPI_STRIDE + wn * 64 + nt * 16],
                              acc[mt][nt], EPI_STRIDE, wmma::mem_row_major);
  __syncthreads();

  {
    int r = tid >> 1;
    int c0 = (tid & 1) * 64;
    int gr = bm + r;
    if (gr < M) {
#pragma unroll
      for (int j = 0; j < 64; j += 4) {
        float4 v = *reinterpret_cast<float4*>(&smf[r * EPI_STRIDE + c0 + j]);
        v.x += sbias[c0 + j + 0]; v.y += sbias[c0 + j + 1];
        v.z += sbias[c0 + j + 2]; v.w += sbias[c0 + j + 3];
        if (FIRST) {
          v.x = fmaxf(v.x, 0.f); v.y = fmaxf(v.y, 0.f);
          v.z = fmaxf(v.z, 0.f); v.w = fmaxf(v.w, 0.f);
          bf162 h0, h1, l0, l1;
          splitbf(v.x, h0.x, l0.x); splitbf(v.y, h0.y, l0.y);
          splitbf(v.z, h1.x, l1.x); splitbf(v.w, h1.y, l1.y);
          size_t off = (size_t)gr * N_ + bn + c0 + j;
          *reinterpret_cast<bf162*>(&g_c1_hi[off]) = h0;
          *reinterpret_cast<bf162*>(&g_c1_hi[off + 2]) = h1;
          *reinterpret_cast<bf162*>(&g_c1_lo[off]) = l0;
          *reinterpret_cast<bf162*>(&g_c1_lo[off + 2]) = l1;
        } else {
          *reinterpret_cast<float4*>(&g_h[(size_t)gr * N_ + bn + c0 + j]) = v;
        }
      }
    }
  }

  if (!FIRST) {
    __syncthreads();
    int c = tid & 127;
    int seg = tid >> 7;
    float b = sbias[c];
    float s = 0.f, q = 0.f;
#pragma unroll
    for (int rr = 0; rr < 64; rr++) {
      int gr = bm + seg * 64 + rr;
      if (gr < M) {
        float v = smf[(seg * 64 + rr) * EPI_STRIDE + c] + b;
        s += v; q += v * v;
      }
    }
    atomicAdd(&g_sum[c], s);
    atomicAdd(&g_sumsq[c], q);
  }
}

// ------------------------- BN finalize / apply ------------------------------
__global__ void bn_finalize(const float* __restrict__ gamma, const float* __restrict__ beta) {
  int n = threadIdx.x;
  const float invM = 1.0f / (float)N_NODES;
  float mean = g_sum[n] * invM;
  float var = g_sumsq[n] * invM - mean * mean;
  float sc = gamma[n] * rsqrtf(var + 1e-5f);
  g_scale[n] = sc;
  g_shift[n] = beta[n] - mean * sc;
}

__global__ void bn_apply(float* __restrict__ out) {
  int i = blockIdx.x * blockDim.x + threadIdx.x;
  const int total4 = N_NODES * EMB / 4;
  if (i >= total4) return;
  int c = (i & 31) << 2;
  float4 h = reinterpret_cast<const float4*>(g_h)[i];
  float4 o;
  o.x = h.x * g_scale[c + 0] + g_shift[c + 0];
  o.y = h.y * g_scale[c + 1] + g_shift[c + 1];
  o.z = h.z * g_scale[c + 2] + g_shift[c + 2];
  o.w = h.w * g_scale[c + 3] + g_shift[c + 3];
  reinterpret_cast<float4*>(out)[i] = o;
}

// ------------------------- launch -------------------------------------------
extern "C" void kernel_launch(void* const* d_in, const int* in_sizes, int n_in,
                              void* d_out, int out_size) {
  const float* node_feats = (const float*)d_in[0];
  const float* edge_feats = (const float*)d_in[1];
  const float* W_edge     = (const float*)d_in[2];
  const float* b_edge     = (const float*)d_in[3];
  const float* W1         = (const float*)d_in[4];
  const float* b1         = (const float*)d_in[5];
  const float* W2         = (const float*)d_in[6];
  const float* b2         = (const float*)d_in[7];
  const float* bn_gamma   = (const float*)d_in[8];
  const float* bn_beta    = (const float*)d_in[9];
  const int*   src        = (const int*)d_in[10];
  const int*   dst        = (const int*)d_in[11];
  float* out = (float*)d_out;

  cudaFuncSetAttribute(wmma_gemm<HID, EMB, true>,
                       cudaFuncAttributeMaxDynamicSharedMemorySize, GEMM_SMEM_BYTES);
  cudaFuncSetAttribute(wmma_gemm<EMB, HID, false>,
                       cudaFuncAttributeMaxDynamicSharedMemorySize, GEMM_SMEM_BYTES);

  const int MTILES = (N_NODES + 127) / 128;  // 391

  zero_kernel<<<(N_NODES + 255) / 256, 256>>>();
  split_weights<<<(EMB * HID + 255) / 256, 256>>>(W1, W2);
  hist_kernel<<<(N_EDGES + 255) / 256, 256>>>(dst);
  scan_phase1<<<SCAN_NBLK, SCAN_BLK>>>();
  scan_phase2<<<1, 32>>>();
  scan_phase3<<<SCAN_NBLK, SCAN_BLK>>>();
  scatter_kernel<<<(N_EDGES + 255) / 256, 256>>>(src, dst);
  aggregate_kernel<<<(N_NODES + 7) / 8, 256>>>(node_feats, edge_feats, W_edge, b_edge);
  dim3 g1(HID / 128, MTILES);
  wmma_gemm<HID, EMB, true><<<g1, 256, GEMM_SMEM_BYTES>>>(b1);
  dim3 g2(EMB / 128, MTILES);
  wmma_gemm<EMB, HID, false><<<g2, 256, GEMM_SMEM_BYTES>>>(b2);
  bn_finalize<<<1, EMB>>>(bn_gamma, bn_beta);
  bn_apply<<<(N_NODES * EMB / 4 + 255) / 256, 256>>>(out);
}

// round 13
// speedup vs baseline: 1.3909x; 1.3909x over previous
#include <cuda_runtime.h>
#include <cuda_bf16.h>
#include <mma.h>
#include <cstdint>

using namespace nvcuda;

#define N_NODES 50000
#define N_EDGES 800000
#define EDGE_DIM 16
#define EMB 128
#define HID 256

#define SCAN_BLK 256
#define SCAN_ITEMS 4
#define SCAN_TILE (SCAN_BLK * SCAN_ITEMS)            // 1024
#define SCAN_NBLK ((N_NODES + SCAN_TILE - 1) / SCAN_TILE)  // 49

typedef __nv_bfloat16 bf16;
typedef __nv_bfloat162 bf162;

// ------------------------- scratch (static device arrays; no allocs) -------
__device__ int   g_cnt[N_NODES];
__device__ int   g_part[SCAN_NBLK];
__device__ int   g_rowptr[N_NODES + 1];
__device__ int   g_cursor[N_NODES];
__device__ int2  g_csr[N_EDGES];                      // (src, eid) packed
__device__ bf16  g_a_hi[(size_t)N_NODES * EMB];
__device__ bf16  g_a_lo[(size_t)N_NODES * EMB];
__device__ bf16  g_c1_hi[(size_t)N_NODES * HID];
__device__ bf16  g_c1_lo[(size_t)N_NODES * HID];
__device__ bf16  g_w1_hi[EMB * HID], g_w1_lo[EMB * HID];
__device__ bf16  g_w2_hi[HID * EMB], g_w2_lo[HID * EMB];
__device__ float g_h[(size_t)N_NODES * EMB];
__device__ float g_sum[EMB];
__device__ float g_sumsq[EMB];
__device__ float g_scale[EMB];
__device__ float g_shift[EMB];

// ------------------------- helpers -----------------------------------------
__device__ __forceinline__ uint32_t smem_u32(const void* p) {
  uint32_t a;
  asm("{ .reg .u64 t; cvta.to.shared.u64 t, %1; cvt.u32.u64 %0, t; }" : "=r"(a) : "l"(p));
  return a;
}
__device__ __forceinline__ void cp16(uint32_t dst, const void* src) {
  asm volatile("cp.async.cg.shared.global [%0], [%1], 16;" :: "r"(dst), "l"(src));
}
__device__ __forceinline__ void cp16z(uint32_t dst, const void* src, uint32_t srcsz) {
  asm volatile("cp.async.cg.shared.global [%0], [%1], 16, %2;"
               :: "r"(dst), "l"(src), "r"(srcsz));
}
#define CP_COMMIT() asm volatile("cp.async.commit_group;" ::: "memory")
#define CP_WAIT1()  asm volatile("cp.async.wait_group 1;" ::: "memory")

__device__ __forceinline__ void splitbf(float x, bf16& hi, bf16& lo) {
  hi = __float2bfloat16(x);
  lo = __float2bfloat16(x - __bfloat162float(hi));
}

// ------------------------- zero scratch ------------------------------------
__global__ void zero_kernel() {
  int i = blockIdx.x * blockDim.x + threadIdx.x;
  if (i < N_NODES) g_cnt[i] = 0;
  if (i < EMB) { g_sum[i] = 0.f; g_sumsq[i] = 0.f; }
}

// ------------------------- split weights ------------------------------------
__global__ void split_weights(const float* __restrict__ W1, const float* __restrict__ W2) {
  int i = blockIdx.x * blockDim.x + threadIdx.x;
  if (i < EMB * HID) {
    splitbf(W1[i], g_w1_hi[i], g_w1_lo[i]);
    splitbf(W2[i], g_w2_hi[i], g_w2_lo[i]);
  }
}

// ------------------------- CSR build ----------------------------------------
__global__ void hist_kernel(const int* __restrict__ dst) {
  int e = blockIdx.x * blockDim.x + threadIdx.x;
  if (e < N_EDGES) atomicAdd(&g_cnt[dst[e]], 1);
}

__global__ __launch_bounds__(SCAN_BLK)
void scan_phase1() {
  __shared__ int wsum[SCAN_BLK / 32];
  int tid = threadIdx.x;
  int base = blockIdx.x * SCAN_TILE + tid * SCAN_ITEMS;
  int s = 0;
#pragma unroll
  for (int j = 0; j < SCAN_ITEMS; j++) {
    int i = base + j;
    if (i < N_NODES) s += g_cnt[i];
  }
#pragma unroll
  for (int o = 16; o > 0; o >>= 1) s += __shfl_down_sync(0xffffffffu, s, o);
  if ((tid & 31) == 0) wsum[tid >> 5] = s;
  __syncthreads();
  if (tid == 0) {
    int t = 0;
#pragma unroll
    for (int w = 0; w < SCAN_BLK / 32; w++) t += wsum[w];
    g_part[blockIdx.x] = t;
  }
}

__global__ void scan_phase2() {
  if (threadIdx.x == 0) {
    int run = 0;
    for (int i = 0; i < SCAN_NBLK; i++) { int v = g_part[i]; g_part[i] = run; run += v; }
    g_rowptr[N_NODES] = run;
  }
}

__global__ __launch_bounds__(SCAN_BLK)
void scan_phase3() {
  __shared__ int wsum[SCAN_BLK / 32];
  int tid = threadIdx.x;
  int lane = tid & 31, w = tid >> 5;
  int base = blockIdx.x * SCAN_TILE + tid * SCAN_ITEMS;
  int v[SCAN_ITEMS];
  int s = 0;
#pragma unroll
  for (int j = 0; j < SCAN_ITEMS; j++) {
    int i = base + j;
    v[j] = (i < N_NODES) ? g_cnt[i] : 0;
    s += v[j];
  }
  int inc = s;
#pragma unroll
  for (int o = 1; o < 32; o <<= 1) {
    int t = __shfl_up_sync(0xffffffffu, inc, o);
    if (lane >= o) inc += t;
  }
  if (lane == 31) wsum[w] = inc;
  __syncthreads();
  if (w == 0) {
    int ws = (lane < SCAN_BLK / 32) ? wsum[lane] : 0;
#pragma unroll
    for (int o = 1; o < SCAN_BLK / 32; o <<= 1) {
      int t = __shfl_up_sync(0xffffffffu, ws, o);
      if (lane >= o) ws += t;
    }
    if (lane < SCAN_BLK / 32) wsum[lane] = ws;
  }
  __syncthreads();
  int excl = inc - s + (w > 0 ? wsum[w - 1] : 0) + g_part[blockIdx.x];
#pragma unroll
  for (int j = 0; j < SCAN_ITEMS; j++) {
    int i = base + j;
    if (i < N_NODES) { g_rowptr[i] = excl; g_cursor[i] = excl; }
    excl += v[j];
  }
}

__global__ void scatter_kernel(const int* __restrict__ src, const int* __restrict__ dst) {
  int e = blockIdx.x * blockDim.x + threadIdx.x;
  if (e >= N_EDGES) return;
  int pos = atomicAdd(&g_cursor[dst[e]], 1);
  g_csr[pos] = make_int2(src[e], e);
}

// ------------------------- gather-aggregate + combine (fused) ----------------
__global__ __launch_bounds__(256)
void aggregate_kernel(const float* __restrict__ nf, const float* __restrict__ ef,
                      const float* __restrict__ W_edge, const float* __restrict__ b_edge) {
  __shared__ float sW[EDGE_DIM][EMB];
  __shared__ float sbe[EMB];
  int tid = threadIdx.x;
  for (int i = tid; i < EDGE_DIM * EMB; i += 256) sW[i >> 7][i & 127] = W_edge[i];
  if (tid < EMB) sbe[tid] = b_edge[tid];
  __syncthreads();

  int w = tid >> 5, lane = tid & 31;
  int n = blockIdx.x * 8 + w;
  if (n >= N_NODES) return;
  int beg = g_rowptr[n], endp = g_rowptr[n + 1];
  float deg = (float)(endp - beg);

  const float4* nf4 = reinterpret_cast<const float4*>(nf);
  const float4* ef4 = reinterpret_cast<const float4*>(ef);

  float4 acc0 = make_float4(0.f, 0.f, 0.f, 0.f);
  float4 acc1 = make_float4(0.f, 0.f, 0.f, 0.f);
  float4 ea0 = make_float4(0.f, 0.f, 0.f, 0.f);
  float4 ea1 = make_float4(0.f, 0.f, 0.f, 0.f);

  int i = beg;
  for (; i + 1 < endp; i += 2) {
    int2 p0 = g_csr[i], p1 = g_csr[i + 1];
    float4 v0 = __ldg(&nf4[(size_t)p0.x * 32 + lane]);
    float4 v1 = __ldg(&nf4[(size_t)p1.x * 32 + lane]);
    acc0.x += v0.x; acc0.y += v0.y; acc0.z += v0.z; acc0.w += v0.w;
    acc1.x += v1.x; acc1.y += v1.y; acc1.z += v1.z; acc1.w += v1.w;
    if (lane < 4) {
      float4 t0 = __ldg(&ef4[(size_t)p0.y * 4 + lane]);
      float4 t1 = __ldg(&ef4[(size_t)p1.y * 4 + lane]);
      ea0.x += t0.x; ea0.y += t0.y; ea0.z += t0.z; ea0.w += t0.w;
      ea1.x += t1.x; ea1.y += t1.y; ea1.z += t1.z; ea1.w += t1.w;
    }
  }
  if (i < endp) {
    int2 p0 = g_csr[i];
    float4 v0 = __ldg(&nf4[(size_t)p0.x * 32 + lane]);
    acc0.x += v0.x; acc0.y += v0.y; acc0.z += v0.z; acc0.w += v0.w;
    if (lane < 4) {
      float4 t0 = __ldg(&ef4[(size_t)p0.y * 4 + lane]);
      ea0.x += t0.x; ea0.y += t0.y; ea0.z += t0.z; ea0.w += t0.w;
    }
  }
  float4 acc = make_float4(acc0.x + acc1.x, acc0.y + acc1.y,
                           acc0.z + acc1.z, acc0.w + acc1.w);
  float4 ea = make_float4(ea0.x + ea1.x, ea0.y + ea1.y, ea0.z + ea1.z, ea0.w + ea1.w);

  int srcl = lane >> 2, comp = lane & 3;
  float ex = __shfl_sync(0xffffffffu, ea.x, srcl);
  float ey = __shfl_sync(0xffffffffu, ea.y, srcl);
  float ez = __shfl_sync(0xffffffffu, ea.z, srcl);
  float ew = __shfl_sync(0xffffffffu, ea.w, srcl);
  float ev = (comp == 0) ? ex : (comp == 1) ? ey : (comp == 2) ? ez : ew;

  int c4 = lane * 4;
  acc.x += deg * sbe[c4 + 0];
  acc.y += deg * sbe[c4 + 1];
  acc.z += deg * sbe[c4 + 2];
  acc.w += deg * sbe[c4 + 3];
#pragma unroll
  for (int k = 0; k < EDGE_DIM; k++) {
    float s = __shfl_sync(0xffffffffu, ev, k);
    acc.x = fmaf(s, sW[k][c4 + 0], acc.x);
    acc.y = fmaf(s, sW[k][c4 + 1], acc.y);
    acc.z = fmaf(s, sW[k][c4 + 2], acc.z);
    acc.w = fmaf(s, sW[k][c4 + 3], acc.w);
  }
  bf162 h0, h1, l0, l1;
  splitbf(acc.x, h0.x, l0.x); splitbf(acc.y, h0.y, l0.y);
  splitbf(acc.z, h1.x, l1.x); splitbf(acc.w, h1.y, l1.y);
  size_t off = (size_t)n * EMB + c4;
  *reinterpret_cast<bf162*>(&g_a_hi[off]) = h0;
  *reinterpret_cast<bf162*>(&g_a_hi[off + 2]) = h1;
  *reinterpret_cast<bf162*>(&g_a_lo[off]) = l0;
  *reinterpret_cast<bf162*>(&g_a_lo[off + 2]) = l1;
}

// ------------------------- pipelined bf16 wmma GEMM (R9-exact config) -------
#define A_STRIDE 48
#define B_STRIDE 144
#define A_HI_OFF 0
#define A_LO_OFF (128 * A_STRIDE)
#define B_HI_OFF (2 * 128 * A_STRIDE)
#define B_LO_OFF (B_HI_OFF + 32 * B_STRIDE)
#define STAGE_ELEMS (B_LO_OFF + 32 * B_STRIDE)
#define STAGE_BYTES (STAGE_ELEMS * 2)
#define GEMM_SMEM_BYTES (2 * STAGE_BYTES)             // 86016
#define EPI_STRIDE 132

template <int N_, int K_, bool FIRST>
__global__ __launch_bounds__(256, 2)
void wmma_gemm(const float* __restrict__ bias) {
  constexpr int M = N_NODES;
  constexpr int CH = K_ / 32;
  const bf16* __restrict__ Ahi = FIRST ? g_a_hi : g_c1_hi;
  const bf16* __restrict__ Alo = FIRST ? g_a_lo : g_c1_lo;
  const bf16* __restrict__ Whi = FIRST ? g_w1_hi : g_w2_hi;
  const bf16* __restrict__ Wlo = FIRST ? g_w1_lo : g_w2_lo;

  extern __shared__ __align__(16) bf16 smb[];
  float* smf = reinterpret_cast<float*>(smb);
  __shared__ float sbias[128];
  const uint32_t smb_b = smem_u32(smb);

  int tid = threadIdx.x;
  int wid = tid >> 5;
  int wm = wid & 3;
  int wn = wid >> 2;
  int bm = blockIdx.y * 128;
  int bn = blockIdx.x * 128;

  if (tid < 128) sbias[tid] = bias[bn + tid];

  wmma::fragment<wmma::accumulator, 16, 16, 16, float> acc[2][4];
#pragma unroll
  for (int mt = 0; mt < 2; mt++)
#pragma unroll
    for (int nt = 0; nt < 4; nt++) wmma::fill_fragment(acc[mt][nt], 0.f);

  auto prefetch = [&](int c, int s) {
    uint32_t base = smb_b + (uint32_t)s * STAGE_BYTES;
    int k0 = c * 32;
#pragma unroll
    for (int l = 0; l < 2; l++) {
      int u = tid + l * 256;
      int ar = u >> 2, as = u & 3;
      int gr = bm + ar;
      uint32_t ok = (gr < M) ? 16u : 0u;
      size_t ago = (size_t)gr * K_ + k0 + as * 8;
      uint32_t aso = (uint32_t)(ar * A_STRIDE + as * 8) * 2;
      cp16z(base + A_HI_OFF * 2 + aso, &Ahi[ago], ok);
      cp16z(base + A_LO_OFF * 2 + aso, &Alo[ago], ok);
      int br = u >> 4, bs = u & 15;
      size_t bgo = (size_t)(k0 + br) * N_ + bn + bs * 8;
      uint32_t bso = (uint32_t)(br * B_STRIDE + bs * 8) * 2;
      cp16(base + B_HI_OFF * 2 + bso, &Whi[bgo]);
      cp16(base + B_LO_OFF * 2 + bso, &Wlo[bgo]);
    }
  };

  prefetch(0, 0); CP_COMMIT();
  prefetch(1, 1); CP_COMMIT();

  for (int c = 0; c < CH; c++) {
    CP_WAIT1();
    __syncthreads();
    const bf16* st = smb + (c & 1) * STAGE_ELEMS;
#pragma unroll
    for (int ks = 0; ks < 2; ks++) {
      wmma::fragment<wmma::matrix_a, 16, 16, 16, bf16, wmma::row_major> ah[2], al[2];
#pragma unroll
      for (int mt = 0; mt < 2; mt++) {
        const bf16* ap = st + (wm * 32 + mt * 16) * A_STRIDE + ks * 16;
        wmma::load_matrix_sync(ah[mt], ap + A_HI_OFF, A_STRIDE);
        wmma::load_matrix_sync(al[mt], ap + A_LO_OFF, A_STRIDE);
      }
#pragma unroll
      for (int nt = 0; nt < 4; nt++) {
        wmma::fragment<wmma::matrix_b, 16, 16, 16, bf16, wmma::row_major> bh, bl;
        const bf16* bp = st + (ks * 16) * B_STRIDE + wn * 64 + nt * 16;
        wmma::load_matrix_sync(bh, bp + B_HI_OFF, B_STRIDE);
        wmma::load_matrix_sync(bl, bp + B_LO_OFF, B_STRIDE);
#pragma unroll
        for (int mt = 0; mt < 2; mt++) {
          wmma::mma_sync(acc[mt][nt], ah[mt], bh, acc[mt][nt]);
          wmma::mma_sync(acc[mt][nt], al[mt], bh, acc[mt][nt]);
          wmma::mma_sync(acc[mt][nt], ah[mt], bl, acc[mt][nt]);
        }
      }
    }
    __syncthreads();
    if (c + 2 < CH) prefetch(c + 2, c & 1);
    CP_COMMIT();
  }

#pragma unroll
  for (int mt = 0; mt < 2; mt++)
#pragma unroll
    for (int nt = 0; nt < 4; nt++)
      wmma::store_matrix_sync(&smf[(wm * 32 + mt * 16) * EPI_STRIDE + wn * 64 + nt * 16],
                              acc[mt][nt], EPI_STRIDE, wmma::mem_row_major);
  __syncthreads();

  {
    int r = tid >> 1;
    int c0 = (tid & 1) * 64;
    int gr = bm + r;
    if (gr < M) {
#pragma unroll
      for (int j = 0; j < 64; j += 4) {
        float4 v = *reinterpret_cast<float4*>(&smf[r * EPI_STRIDE + c0 + j]);
        v.x += sbias[c0 + j + 0]; v.y += sbias[c0 + j + 1];
        v.z += sbias[c0 + j + 2]; v.w += sbias[c0 + j + 3];
        if (FIRST) {
          v.x = fmaxf(v.x, 0.f); v.y = fmaxf(v.y, 0.f);
          v.z = fmaxf(v.z, 0.f); v.w = fmaxf(v.w, 0.f);
          bf162 h0, h1, l0, l1;
          splitbf(v.x, h0.x, l0.x); splitbf(v.y, h0.y, l0.y);
          splitbf(v.z, h1.x, l1.x); splitbf(v.w, h1.y, l1.y);
          size_t off = (size_t)gr * N_ + bn + c0 + j;
          *reinterpret_cast<bf162*>(&g_c1_hi[off]) = h0;
          *reinterpret_cast<bf162*>(&g_c1_hi[off + 2]) = h1;
          *reinterpret_cast<bf162*>(&g_c1_lo[off]) = l0;
          *reinterpret_cast<bf162*>(&g_c1_lo[off + 2]) = l1;
        } else {
          *reinterpret_cast<float4*>(&g_h[(size_t)gr * N_ + bn + c0 + j]) = v;
        }
      }
    }
  }

  if (!FIRST) {
    __syncthreads();
    int c = tid & 127;
    int seg = tid >> 7;
    float b = sbias[c];
    float s = 0.f, q = 0.f;
#pragma unroll
    for (int rr = 0; rr < 64; rr++) {
      int gr = bm + seg * 64 + rr;
      if (gr < M) {
        float v = smf[(seg * 64 + rr) * EPI_STRIDE + c] + b;
        s += v; q += v * v;
      }
    }
    atomicAdd(&g_sum[c], s);
    atomicAdd(&g_sumsq[c], q);
  }
}

// ------------------------- BN finalize / apply ------------------------------
__global__ void bn_finalize(const float* __restrict__ gamma, const float* __restrict__ beta) {
  int n = threadIdx.x;
  const float invM = 1.0f / (float)N_NODES;
  float mean = g_sum[n] * invM;
  float var = g_sumsq[n] * invM - mean * mean;
  float sc = gamma[n] * rsqrtf(var + 1e-5f);
  g_scale[n] = sc;
  g_shift[n] = beta[n] - mean * sc;
}

__global__ void bn_apply(float* __restrict__ out) {
  int i = blockIdx.x * blockDim.x + threadIdx.x;
  const int total4 = N_NODES * EMB / 4;
  if (i >= total4) return;
  int c = (i & 31) << 2;
  float4 h = reinterpret_cast<const float4*>(g_h)[i];
  float4 o;
  o.x = h.x * g_scale[c + 0] + g_shift[c + 0];
  o.y = h.y * g_scale[c + 1] + g_shift[c + 1];
  o.z = h.z * g_scale[c + 2] + g_shift[c + 2];
  o.w = h.w * g_scale[c + 3] + g_shift[c + 3];
  reinterpret_cast<float4*>(out)[i] = o;
}

// ------------------------- launch -------------------------------------------
extern "C" void kernel_launch(void* const* d_in, const int* in_sizes, int n_in,
                              void* d_out, int out_size) {
  const float* node_feats = (const float*)d_in[0];
  const float* edge_feats = (const float*)d_in[1];
  const float* W_edge     = (const float*)d_in[2];
  const float* b_edge     = (const float*)d_in[3];
  const float* W1         = (const float*)d_in[4];
  const float* b1         = (const float*)d_in[5];
  const float* W2         = (const float*)d_in[6];
  const float* b2         = (const float*)d_in[7];
  const float* bn_gamma   = (const float*)d_in[8];
  const float* bn_beta    = (const float*)d_in[9];
  const int*   src        = (const int*)d_in[10];
  const int*   dst        = (const int*)d_in[11];
  float* out = (float*)d_out;

  cudaFuncSetAttribute(wmma_gemm<HID, EMB, true>,
                       cudaFuncAttributeMaxDynamicSharedMemorySize, GEMM_SMEM_BYTES);
  cudaFuncSetAttribute(wmma_gemm<EMB, HID, false>,
                       cudaFuncAttributeMaxDynamicSharedMemorySize, GEMM_SMEM_BYTES);

  const int MTILES = (N_NODES + 127) / 128;  // 391

  zero_kernel<<<(N_NODES + 255) / 256, 256>>>();
  split_weights<<<(EMB * HID + 255) / 256, 256>>>(W1, W2);
  hist_kernel<<<(N_EDGES + 255) / 256, 256>>>(dst);
  scan_phase1<<<SCAN_NBLK, SCAN_BLK>>>();
  scan_phase2<<<1, 32>>>();
  scan_phase3<<<SCAN_NBLK, SCAN_BLK>>>();
  scatter_kernel<<<(N_EDGES + 255) / 256, 256>>>(src, dst);
  aggregate_kernel<<<(N_NODES + 7) / 8, 256>>>(node_feats, edge_feats, W_edge, b_edge);
  dim3 g1(HID / 128, MTILES);
  wmma_gemm<HID, EMB, true><<<g1, 256, GEMM_SMEM_BYTES>>>(b1);
  dim3 g2(EMB / 128, MTILES);
  wmma_gemm<EMB, HID, false><<<g2, 256, GEMM_SMEM_BYTES>>>(b2);
  bn_finalize<<<1, EMB>>>(bn_gamma, bn_beta);
  bn_apply<<<(N_NODES * EMB / 4 + 255) / 256, 256>>>(out);
}

// round 14
// speedup vs baseline: 1.6269x; 1.1697x over previous
#include <cuda_runtime.h>
#include <cuda_bf16.h>
#include <mma.h>
#include <cstdint>

using namespace nvcuda;

#define N_NODES 50000
#define N_EDGES 800000
#define EDGE_DIM 16
#define EMB 128
#define HID 256

#define SCAN_BLK 256
#define SCAN_ITEMS 4
#define SCAN_TILE (SCAN_BLK * SCAN_ITEMS)            // 1024
#define SCAN_NBLK ((N_NODES + SCAN_TILE - 1) / SCAN_TILE)  // 49

typedef __nv_bfloat16 bf16;
typedef __nv_bfloat162 bf162;

// ------------------------- scratch (static device arrays; no allocs) -------
__device__ int   g_cnt[N_NODES];
__device__ int   g_part[SCAN_NBLK];
__device__ int   g_rowptr[N_NODES + 1];
__device__ int   g_cursor[N_NODES];
__device__ int2  g_csr[N_EDGES];                      // (src, eid) packed
__device__ bf16  g_a_hi[(size_t)N_NODES * EMB];
__device__ bf16  g_a_lo[(size_t)N_NODES * EMB];
__device__ bf16  g_w1_hi[EMB * HID], g_w1_lo[EMB * HID];
__device__ bf16  g_w2_hi[HID * EMB], g_w2_lo[HID * EMB];
__device__ float g_h[(size_t)N_NODES * EMB];
__device__ float g_sum[EMB];
__device__ float g_sumsq[EMB];
__device__ float g_scale[EMB];
__device__ float g_shift[EMB];

// ------------------------- helpers -----------------------------------------
__device__ __forceinline__ uint32_t smem_u32(const void* p) {
  uint32_t a;
  asm("{ .reg .u64 t; cvta.to.shared.u64 t, %1; cvt.u32.u64 %0, t; }" : "=r"(a) : "l"(p));
  return a;
}
__device__ __forceinline__ void cp16(uint32_t dst, const void* src) {
  asm volatile("cp.async.cg.shared.global [%0], [%1], 16;" :: "r"(dst), "l"(src));
}
__device__ __forceinline__ void cp16z(uint32_t dst, const void* src, uint32_t srcsz) {
  asm volatile("cp.async.cg.shared.global [%0], [%1], 16, %2;"
               :: "r"(dst), "l"(src), "r"(srcsz));
}
#define CP_COMMIT() asm volatile("cp.async.commit_group;" ::: "memory")
#define CP_WAIT1()  asm volatile("cp.async.wait_group 1;" ::: "memory")
#define CP_WAIT0()  asm volatile("cp.async.wait_group 0;" ::: "memory")

__device__ __forceinline__ void splitbf(float x, bf16& hi, bf16& lo) {
  hi = __float2bfloat16(x);
  lo = __float2bfloat16(x - __bfloat162float(hi));
}

// ------------------------- zero scratch ------------------------------------
__global__ void zero_kernel() {
  int i = blockIdx.x * blockDim.x + threadIdx.x;
  if (i < N_NODES) g_cnt[i] = 0;
  if (i < EMB) { g_sum[i] = 0.f; g_sumsq[i] = 0.f; }
}

// ------------------------- split weights ------------------------------------
__global__ void split_weights(const float* __restrict__ W1, const float* __restrict__ W2) {
  int i = blockIdx.x * blockDim.x + threadIdx.x;
  if (i < EMB * HID) {
    splitbf(W1[i], g_w1_hi[i], g_w1_lo[i]);
    splitbf(W2[i], g_w2_hi[i], g_w2_lo[i]);
  }
}

// ------------------------- CSR build ----------------------------------------
__global__ void hist_kernel(const int* __restrict__ dst) {
  int e = blockIdx.x * blockDim.x + threadIdx.x;
  if (e < N_EDGES) atomicAdd(&g_cnt[dst[e]], 1);
}

__global__ __launch_bounds__(SCAN_BLK)
void scan_phase1() {
  __shared__ int wsum[SCAN_BLK / 32];
  int tid = threadIdx.x;
  int base = blockIdx.x * SCAN_TILE + tid * SCAN_ITEMS;
  int s = 0;
#pragma unroll
  for (int j = 0; j < SCAN_ITEMS; j++) {
    int i = base + j;
    if (i < N_NODES) s += g_cnt[i];
  }
#pragma unroll
  for (int o = 16; o > 0; o >>= 1) s += __shfl_down_sync(0xffffffffu, s, o);
  if ((tid & 31) == 0) wsum[tid >> 5] = s;
  __syncthreads();
  if (tid == 0) {
    int t = 0;
#pragma unroll
    for (int w = 0; w < SCAN_BLK / 32; w++) t += wsum[w];
    g_part[blockIdx.x] = t;
  }
}

__global__ void scan_phase2() {
  if (threadIdx.x == 0) {
    int run = 0;
    for (int i = 0; i < SCAN_NBLK; i++) { int v = g_part[i]; g_part[i] = run; run += v; }
    g_rowptr[N_NODES] = run;
  }
}

__global__ __launch_bounds__(SCAN_BLK)
void scan_phase3() {
  __shared__ int wsum[SCAN_BLK / 32];
  int tid = threadIdx.x;
  int lane = tid & 31, w = tid >> 5;
  int base = blockIdx.x * SCAN_TILE + tid * SCAN_ITEMS;
  int v[SCAN_ITEMS];
  int s = 0;
#pragma unroll
  for (int j = 0; j < SCAN_ITEMS; j++) {
    int i = base + j;
    v[j] = (i < N_NODES) ? g_cnt[i] : 0;
    s += v[j];
  }
  int inc = s;
#pragma unroll
  for (int o = 1; o < 32; o <<= 1) {
    int t = __shfl_up_sync(0xffffffffu, inc, o);
    if (lane >= o) inc += t;
  }
  if (lane == 31) wsum[w] = inc;
  __syncthreads();
  if (w == 0) {
    int ws = (lane < SCAN_BLK / 32) ? wsum[lane] : 0;
#pragma unroll
    for (int o = 1; o < SCAN_BLK / 32; o <<= 1) {
      int t = __shfl_up_sync(0xffffffffu, ws, o);
      if (lane >= o) ws += t;
    }
    if (lane < SCAN_BLK / 32) wsum[lane] = ws;
  }
  __syncthreads();
  int excl = inc - s + (w > 0 ? wsum[w - 1] : 0) + g_part[blockIdx.x];
#pragma unroll
  for (int j = 0; j < SCAN_ITEMS; j++) {
    int i = base + j;
    if (i < N_NODES) { g_rowptr[i] = excl; g_cursor[i] = excl; }
    excl += v[j];
  }
}

__global__ void scatter_kernel(const int* __restrict__ src, const int* __restrict__ dst) {
  int e = blockIdx.x * blockDim.x + threadIdx.x;
  if (e >= N_EDGES) return;
  int pos = atomicAdd(&g_cursor[dst[e]], 1);
  g_csr[pos] = make_int2(src[e], e);
}

// ------------------------- gather-aggregate + combine (fused) ----------------
__global__ __launch_bounds__(256)
void aggregate_kernel(const float* __restrict__ nf, const float* __restrict__ ef,
                      const float* __restrict__ W_edge, const float* __restrict__ b_edge) {
  __shared__ float sW[EDGE_DIM][EMB];
  __shared__ float sbe[EMB];
  int tid = threadIdx.x;
  for (int i = tid; i < EDGE_DIM * EMB; i += 256) sW[i >> 7][i & 127] = W_edge[i];
  if (tid < EMB) sbe[tid] = b_edge[tid];
  __syncthreads();

  int w = tid >> 5, lane = tid & 31;
  int n = blockIdx.x * 8 + w;
  if (n >= N_NODES) return;
  int beg = g_rowptr[n], endp = g_rowptr[n + 1];
  float deg = (float)(endp - beg);

  const float4* nf4 = reinterpret_cast<const float4*>(nf);
  const float4* ef4 = reinterpret_cast<const float4*>(ef);

  float4 acc0 = make_float4(0.f, 0.f, 0.f, 0.f);
  float4 acc1 = make_float4(0.f, 0.f, 0.f, 0.f);
  float4 ea0 = make_float4(0.f, 0.f, 0.f, 0.f);
  float4 ea1 = make_float4(0.f, 0.f, 0.f, 0.f);

  int i = beg;
  for (; i + 1 < endp; i += 2) {
    int2 p0 = g_csr[i], p1 = g_csr[i + 1];
    float4 v0 = __ldg(&nf4[(size_t)p0.x * 32 + lane]);
    float4 v1 = __ldg(&nf4[(size_t)p1.x * 32 + lane]);
    acc0.x += v0.x; acc0.y += v0.y; acc0.z += v0.z; acc0.w += v0.w;
    acc1.x += v1.x; acc1.y += v1.y; acc1.z += v1.z; acc1.w += v1.w;
    if (lane < 4) {
      float4 t0 = __ldg(&ef4[(size_t)p0.y * 4 + lane]);
      float4 t1 = __ldg(&ef4[(size_t)p1.y * 4 + lane]);
      ea0.x += t0.x; ea0.y += t0.y; ea0.z += t0.z; ea0.w += t0.w;
      ea1.x += t1.x; ea1.y += t1.y; ea1.z += t1.z; ea1.w += t1.w;
    }
  }
  if (i < endp) {
    int2 p0 = g_csr[i];
    float4 v0 = __ldg(&nf4[(size_t)p0.x * 32 + lane]);
    acc0.x += v0.x; acc0.y += v0.y; acc0.z += v0.z; acc0.w += v0.w;
    if (lane < 4) {
      float4 t0 = __ldg(&ef4[(size_t)p0.y * 4 + lane]);
      ea0.x += t0.x; ea0.y += t0.y; ea0.z += t0.z; ea0.w += t0.w;
    }
  }
  float4 acc = make_float4(acc0.x + acc1.x, acc0.y + acc1.y,
                           acc0.z + acc1.z, acc0.w + acc1.w);
  float4 ea = make_float4(ea0.x + ea1.x, ea0.y + ea1.y, ea0.z + ea1.z, ea0.w + ea1.w);

  int srcl = lane >> 2, comp = lane & 3;
  float ex = __shfl_sync(0xffffffffu, ea.x, srcl);
  float ey = __shfl_sync(0xffffffffu, ea.y, srcl);
  float ez = __shfl_sync(0xffffffffu, ea.z, srcl);
  float ew = __shfl_sync(0xffffffffu, ea.w, srcl);
  float ev = (comp == 0) ? ex : (comp == 1) ? ey : (comp == 2) ? ez : ew;

  int c4 = lane * 4;
  acc.x += deg * sbe[c4 + 0];
  acc.y += deg * sbe[c4 + 1];
  acc.z += deg * sbe[c4 + 2];
  acc.w += deg * sbe[c4 + 3];
#pragma unroll
  for (int k = 0; k < EDGE_DIM; k++) {
    float s = __shfl_sync(0xffffffffu, ev, k);
    acc.x = fmaf(s, sW[k][c4 + 0], acc.x);
    acc.y = fmaf(s, sW[k][c4 + 1], acc.y);
    acc.z = fmaf(s, sW[k][c4 + 2], acc.z);
    acc.w = fmaf(s, sW[k][c4 + 3], acc.w);
  }
  bf162 h0, h1, l0, l1;
  splitbf(acc.x, h0.x, l0.x); splitbf(acc.y, h0.y, l0.y);
  splitbf(acc.z, h1.x, l1.x); splitbf(acc.w, h1.y, l1.y);
  size_t off = (size_t)n * EMB + c4;
  *reinterpret_cast<bf162*>(&g_a_hi[off]) = h0;
  *reinterpret_cast<bf162*>(&g_a_hi[off + 2]) = h1;
  *reinterpret_cast<bf162*>(&g_a_lo[off]) = l0;
  *reinterpret_cast<bf162*>(&g_a_lo[off + 2]) = l1;
}

// ------------------------- fused MLP (gemm1 + gemm2, c1 stays in smem) ------
#define A_STRIDE 48
#define B_STRIDE 144
#define A_HI_OFF 0
#define A_LO_OFF (128 * A_STRIDE)
#define B_HI_OFF (2 * 128 * A_STRIDE)
#define B_LO_OFF (B_HI_OFF + 32 * B_STRIDE)
#define STAGE_ELEMS (B_LO_OFF + 32 * B_STRIDE)        // 21504 bf16
#define STAGE_BYTES (STAGE_ELEMS * 2)                 // 43008
#define EPI_STRIDE 132

// c1 tile in smem: 128 rows x 256 K, hi+lo planes, stride 264
// (row start bank = (132r)%32 = 4r mod 32 -> conflict-free over 8 rows)
#define C1_STRIDE 264
#define C1_LO (128 * C1_STRIDE)                       // 33792 elems
#define C1_ELEMS (2 * 128 * C1_STRIDE)                // 67584 elems (135168 B)
#define STG_OFF C1_ELEMS                              // stage area elem offset
// phase-B B-only stages
#define BST_ELEMS (2 * 32 * B_STRIDE)                 // 9216 elems / stage
#define BST_BYTES (BST_ELEMS * 2)                     // 18432
#define FUSED_SMEM_BYTES (C1_ELEMS * 2 + 2 * STAGE_BYTES)  // 221184

__global__ __launch_bounds__(256, 1)
void fused_mlp(const float* __restrict__ b1, const float* __restrict__ b2) {
  constexpr int M = N_NODES;
  extern __shared__ __align__(16) bf16 smb[];
  bf16* c1 = smb;                                      // hi at 0, lo at C1_LO
  bf16* stg = smb + STG_OFF;
  float* smf = reinterpret_cast<float*>(smb + STG_OFF);
  __shared__ float sb1[HID];
  __shared__ float sb2[EMB];
  const uint32_t smb_b = smem_u32(smb);
  const uint32_t stg_b = smb_b + STG_OFF * 2;

  int tid = threadIdx.x;
  int wid = tid >> 5;
  int wm = wid & 3;
  int wn = wid >> 2;
  int bm = blockIdx.x * 128;

  if (tid < HID) sb1[tid] = b1[tid];
  if (tid < EMB) sb2[tid] = b2[tid];

  wmma::fragment<wmma::accumulator, 16, 16, 16, float> acc[2][4];

  // ===================== phase A: c1 = relu(agg @ W1 + b1) ==================
#pragma unroll
  for (int h = 0; h < 2; h++) {
    int bn = h * 128;
#pragma unroll
    for (int mt = 0; mt < 2; mt++)
#pragma unroll
      for (int nt = 0; nt < 4; nt++) wmma::fill_fragment(acc[mt][nt], 0.f);

    auto prefetchA = [&](int c, int s) {
      uint32_t base = stg_b + (uint32_t)s * STAGE_BYTES;
      int k0 = c * 32;
#pragma unroll
      for (int l = 0; l < 2; l++) {
        int u = tid + l * 256;
        int ar = u >> 2, as_ = u & 3;
        int gr = bm + ar;
        uint32_t ok = (gr < M) ? 16u : 0u;
        size_t ago = (size_t)gr * EMB + k0 + as_ * 8;
        uint32_t aso = (uint32_t)(ar * A_STRIDE + as_ * 8) * 2;
        cp16z(base + aso, &g_a_hi[ago], ok);
        cp16z(base + A_LO_OFF * 2 + aso, &g_a_lo[ago], ok);
        int br = u >> 4, bs = u & 15;
        size_t bgo = (size_t)(k0 + br) * HID + bn + bs * 8;
        uint32_t bso = (uint32_t)(br * B_STRIDE + bs * 8) * 2;
        cp16(base + B_HI_OFF * 2 + bso, &g_w1_hi[bgo]);
        cp16(base + B_LO_OFF * 2 + bso, &g_w1_lo[bgo]);
      }
    };

    __syncthreads();   // stage/smf area free before overwriting
    prefetchA(0, 0); CP_COMMIT();
    prefetchA(1, 1); CP_COMMIT();

    for (int c = 0; c < 4; c++) {
      CP_WAIT1();
      __syncthreads();
      const bf16* st = stg + (c & 1) * STAGE_ELEMS;
#pragma unroll
      for (int ks = 0; ks < 2; ks++) {
        wmma::fragment<wmma::matrix_a, 16, 16, 16, bf16, wmma::row_major> ah[2], al[2];
#pragma unroll
        for (int mt = 0; mt < 2; mt++) {
          const bf16* ap = st + (wm * 32 + mt * 16) * A_STRIDE + ks * 16;
          wmma::load_matrix_sync(ah[mt], ap + A_HI_OFF, A_STRIDE);
          wmma::load_matrix_sync(al[mt], ap + A_LO_OFF, A_STRIDE);
        }
#pragma unroll
        for (int nt = 0; nt < 4; nt++) {
          wmma::fragment<wmma::matrix_b, 16, 16, 16, bf16, wmma::row_major> bh, bl;
          const bf16* bp = st + (ks * 16) * B_STRIDE + wn * 64 + nt * 16;
          wmma::load_matrix_sync(bh, bp + B_HI_OFF, B_STRIDE);
          wmma::load_matrix_sync(bl, bp + B_LO_OFF, B_STRIDE);
#pragma unroll
          for (int mt = 0; mt < 2; mt++) {
            wmma::mma_sync(acc[mt][nt], ah[mt], bh, acc[mt][nt]);
            wmma::mma_sync(acc[mt][nt], al[mt], bh, acc[mt][nt]);
            wmma::mma_sync(acc[mt][nt], ah[mt], bl, acc[mt][nt]);
          }
        }
      }
      __syncthreads();
      if (c + 2 < 4) prefetchA(c + 2, c & 1);
      CP_COMMIT();
    }

    // epilogue: acc -> smf -> bias/relu/split -> c1 smem planes
    CP_WAIT0();
    __syncthreads();
#pragma unroll
    for (int mt = 0; mt < 2; mt++)
#pragma unroll
      for (int nt = 0; nt < 4; nt++)
        wmma::store_matrix_sync(&smf[(wm * 32 + mt * 16) * EPI_STRIDE + wn * 64 + nt * 16],
                                acc[mt][nt], EPI_STRIDE, wmma::mem_row_major);
    __syncthreads();
    {
      int r = tid >> 1;
      int c0 = (tid & 1) * 64;
#pragma unroll
      for (int j = 0; j < 64; j += 4) {
        float4 v = *reinterpret_cast<float4*>(&smf[r * EPI_STRIDE + c0 + j]);
        v.x = fmaxf(v.x + sb1[bn + c0 + j + 0], 0.f);
        v.y = fmaxf(v.y + sb1[bn + c0 + j + 1], 0.f);
        v.z = fmaxf(v.z + sb1[bn + c0 + j + 2], 0.f);
        v.w = fmaxf(v.w + sb1[bn + c0 + j + 3], 0.f);
        bf162 h0, h1, l0, l1;
        splitbf(v.x, h0.x, l0.x); splitbf(v.y, h0.y, l0.y);
        splitbf(v.z, h1.x, l1.x); splitbf(v.w, h1.y, l1.y);
        int off = r * C1_STRIDE + bn + c0 + j;
        *reinterpret_cast<bf162*>(&c1[off]) = h0;
        *reinterpret_cast<bf162*>(&c1[off + 2]) = h1;
        *reinterpret_cast<bf162*>(&c1[C1_LO + off]) = l0;
        *reinterpret_cast<bf162*>(&c1[C1_LO + off + 2]) = l1;
      }
    }
    __syncthreads();
  }

  // ===================== phase B: h = c1 @ W2 + b2 ==========================
#pragma unroll
  for (int mt = 0; mt < 2; mt++)
#pragma unroll
    for (int nt = 0; nt < 4; nt++) wmma::fill_fragment(acc[mt][nt], 0.f);

  auto prefetchB = [&](int c, int s) {
    uint32_t base = stg_b + (uint32_t)s * BST_BYTES;
    int k0 = c * 32;
#pragma unroll
    for (int l = 0; l < 2; l++) {
      int u = tid + l * 256;
      int br = u >> 4, bs = u & 15;
      size_t bgo = (size_t)(k0 + br) * EMB + bs * 8;
      uint32_t bso = (uint32_t)(br * B_STRIDE + bs * 8) * 2;
      cp16(base + bso, &g_w2_hi[bgo]);
      cp16(base + (uint32_t)(32 * B_STRIDE) * 2 + bso, &g_w2_lo[bgo]);
    }
  };

  prefetchB(0, 0); CP_COMMIT();
  prefetchB(1, 1); CP_COMMIT();

  for (int c = 0; c < 8; c++) {
    CP_WAIT1();
    __syncthreads();
    const bf16* bst = stg + (c & 1) * BST_ELEMS;
#pragma unroll
    for (int ks = 0; ks < 2; ks++) {
      wmma::fragment<wmma::matrix_a, 16, 16, 16, bf16, wmma::row_major> ah[2], al[2];
#pragma unroll
      for (int mt = 0; mt < 2; mt++) {
        const bf16* ap = c1 + (wm * 32 + mt * 16) * C1_STRIDE + c * 32 + ks * 16;
        wmma::load_matrix_sync(ah[mt], ap, C1_STRIDE);
        wmma::load_matrix_sync(al[mt], ap + C1_LO, C1_STRIDE);
      }
#pragma unroll
      for (int nt = 0; nt < 4; nt++) {
        wmma::fragment<wmma::matrix_b, 16, 16, 16, bf16, wmma::row_major> bh, bl;
        const bf16* bp = bst + (ks * 16) * B_STRIDE + wn * 64 + nt * 16;
        wmma::load_matrix_sync(bh, bp, B_STRIDE);
        wmma::load_matrix_sync(bl, bp + 32 * B_STRIDE, B_STRIDE);
#pragma unroll
        for (int mt = 0; mt < 2; mt++) {
          wmma::mma_sync(acc[mt][nt], ah[mt], bh, acc[mt][nt]);
          wmma::mma_sync(acc[mt][nt], al[mt], bh, acc[mt][nt]);
          wmma::mma_sync(acc[mt][nt], ah[mt], bl, acc[mt][nt]);
        }
      }
    }
    __syncthreads();
    if (c + 2 < 8) prefetchB(c + 2, c & 1);
    CP_COMMIT();
  }

  // epilogue: bias, store h, fused BN stats
  CP_WAIT0();
  __syncthreads();
#pragma unroll
  for (int mt = 0; mt < 2; mt++)
#pragma unroll
    for (int nt = 0; nt < 4; nt++)
      wmma::store_matrix_sync(&smf[(wm * 32 + mt * 16) * EPI_STRIDE + wn * 64 + nt * 16],
                              acc[mt][nt], EPI_STRIDE, wmma::mem_row_major);
  __syncthreads();
  {
    int r = tid >> 1;
    int c0 = (tid & 1) * 64;
    int gr = bm + r;
    if (gr < M) {
#pragma unroll
      for (int j = 0; j < 64; j += 4) {
        float4 v = *reinterpret_cast<float4*>(&smf[r * EPI_STRIDE + c0 + j]);
        v.x += sb2[c0 + j + 0]; v.y += sb2[c0 + j + 1];
        v.z += sb2[c0 + j + 2]; v.w += sb2[c0 + j + 3];
        *reinterpret_cast<float4*>(&g_h[(size_t)gr * EMB + c0 + j]) = v;
      }
    }
  }
  __syncthreads();
  {
    int cc = tid & 127;
    int seg = tid >> 7;
    float b = sb2[cc];
    float s = 0.f, q = 0.f;
#pragma unroll
    for (int rr = 0; rr < 64; rr++) {
      int gr = bm + seg * 64 + rr;
      if (gr < M) {
        float v = smf[(seg * 64 + rr) * EPI_STRIDE + cc] + b;
        s += v; q += v * v;
      }
    }
    atomicAdd(&g_sum[cc], s);
    atomicAdd(&g_sumsq[cc], q);
  }
}

// ------------------------- BN finalize / apply ------------------------------
__global__ void bn_finalize(const float* __restrict__ gamma, const float* __restrict__ beta) {
  int n = threadIdx.x;
  const float invM = 1.0f / (float)N_NODES;
  float mean = g_sum[n] * invM;
  float var = g_sumsq[n] * invM - mean * mean;
  float sc = gamma[n] * rsqrtf(var + 1e-5f);
  g_scale[n] = sc;
  g_shift[n] = beta[n] - mean * sc;
}

__global__ void bn_apply(float* __restrict__ out) {
  int i = blockIdx.x * blockDim.x + threadIdx.x;
  const int total4 = N_NODES * EMB / 4;
  if (i >= total4) return;
  int c = (i & 31) << 2;
  float4 h = reinterpret_cast<const float4*>(g_h)[i];
  float4 o;
  o.x = h.x * g_scale[c + 0] + g_shift[c + 0];
  o.y = h.y * g_scale[c + 1] + g_shift[c + 1];
  o.z = h.z * g_scale[c + 2] + g_shift[c + 2];
  o.w = h.w * g_scale[c + 3] + g_shift[c + 3];
  reinterpret_cast<float4*>(out)[i] = o;
}

// ------------------------- launch -------------------------------------------
extern "C" void kernel_launch(void* const* d_in, const int* in_sizes, int n_in,
                              void* d_out, int out_size) {
  const float* node_feats = (const float*)d_in[0];
  const float* edge_feats = (const float*)d_in[1];
  const float* W_edge     = (const float*)d_in[2];
  const float* b_edge     = (const float*)d_in[3];
  const float* W1         = (const float*)d_in[4];
  const float* b1         = (const float*)d_in[5];
  const float* W2         = (const float*)d_in[6];
  const float* b2         = (const float*)d_in[7];
  const float* bn_gamma   = (const float*)d_in[8];
  const float* bn_beta    = (const float*)d_in[9];
  const int*   src        = (const int*)d_in[10];
  const int*   dst        = (const int*)d_in[11];
  float* out = (float*)d_out;

  cudaFuncSetAttribute(fused_mlp,
                       cudaFuncAttributeMaxDynamicSharedMemorySize, FUSED_SMEM_BYTES);

  const int MTILES = (N_NODES + 127) / 128;  // 391

  zero_kernel<<<(N_NODES + 255) / 256, 256>>>();
  split_weights<<<(EMB * HID + 255) / 256, 256>>>(W1, W2);
  hist_kernel<<<(N_EDGES + 255) / 256, 256>>>(dst);
  scan_phase1<<<SCAN_NBLK, SCAN_BLK>>>();
  scan_phase2<<<1, 32>>>();
  scan_phase3<<<SCAN_NBLK, SCAN_BLK>>>();
  scatter_kernel<<<(N_EDGES + 255) / 256, 256>>>(src, dst);
  aggregate_kernel<<<(N_NODES + 7) / 8, 256>>>(node_feats, edge_feats, W_edge, b_edge);
  fused_mlp<<<MTILES, 256, FUSED_SMEM_BYTES>>>(b1, b2);
  bn_finalize<<<1, EMB>>>(bn_gamma, bn_beta);
  bn_apply<<<(N_NODES * EMB / 4 + 255) / 256, 256>>>(out);
}

// round 15
// speedup vs baseline: 2.0161x; 1.2392x over previous
#include <cuda_runtime.h>
#include <cuda_fp16.h>
#include <mma.h>
#include <cstdint>

using namespace nvcuda;

#define N_NODES 50000
#define N_EDGES 800000
#define EDGE_DIM 16
#define EMB 128
#define HID 256

#define SCAN_BLK 256
#define SCAN_ITEMS 4
#define SCAN_TILE (SCAN_BLK * SCAN_ITEMS)            // 1024
#define SCAN_NBLK ((N_NODES + SCAN_TILE - 1) / SCAN_TILE)  // 49

typedef __half fp16;
typedef __half2 fp162;

// ------------------------- scratch (static device arrays; no allocs) -------
__device__ int   g_cnt[N_NODES];
__device__ int   g_part[SCAN_NBLK];
__device__ int   g_rowptr[N_NODES + 1];
__device__ int   g_cursor[N_NODES];
__device__ int2  g_csr[N_EDGES];                      // (src, eid) packed
__device__ fp16  g_a_hi[(size_t)N_NODES * EMB];       // fp16 2-plane split of agg
__device__ fp16  g_a_lo[(size_t)N_NODES * EMB];
__device__ fp16  g_w1h[EMB * HID];                    // single fp16 plane weights
__device__ fp16  g_w2h[HID * EMB];
__device__ float g_h[(size_t)N_NODES * EMB];
__device__ float g_sum[EMB];
__device__ float g_sumsq[EMB];

// ------------------------- helpers -----------------------------------------
__device__ __forceinline__ uint32_t smem_u32(const void* p) {
  uint32_t a;
  asm("{ .reg .u64 t; cvta.to.shared.u64 t, %1; cvt.u32.u64 %0, t; }" : "=r"(a) : "l"(p));
  return a;
}
__device__ __forceinline__ void cp16(uint32_t dst, const void* src) {
  asm volatile("cp.async.cg.shared.global [%0], [%1], 16;" :: "r"(dst), "l"(src));
}
__device__ __forceinline__ void cp16z(uint32_t dst, const void* src, uint32_t srcsz) {
  asm volatile("cp.async.cg.shared.global [%0], [%1], 16, %2;"
               :: "r"(dst), "l"(src), "r"(srcsz));
}
#define CP_COMMIT() asm volatile("cp.async.commit_group;" ::: "memory")
#define CP_WAIT1()  asm volatile("cp.async.wait_group 1;" ::: "memory")
#define CP_WAIT0()  asm volatile("cp.async.wait_group 0;" ::: "memory")

__device__ __forceinline__ void splith(float x, fp16& hi, fp16& lo) {
  hi = __float2half(x);
  lo = __float2half(x - __half2float(hi));
}

// ------------------------- init: zero + weight cast (merged) ----------------
__global__ void init_kernel(const float* __restrict__ W1, const float* __restrict__ W2) {
  int i = blockIdx.x * blockDim.x + threadIdx.x;
  if (i < N_NODES) g_cnt[i] = 0;
  if (i < EMB) { g_sum[i] = 0.f; g_sumsq[i] = 0.f; }
  if (i < EMB * HID) {
    g_w1h[i] = __float2half(W1[i]);
    g_w2h[i] = __float2half(W2[i]);
  }
}

// ------------------------- CSR build ----------------------------------------
__global__ void hist_kernel(const int* __restrict__ dst) {
  int e = blockIdx.x * blockDim.x + threadIdx.x;
  if (e < N_EDGES) atomicAdd(&g_cnt[dst[e]], 1);
}

__global__ __launch_bounds__(SCAN_BLK)
void scan_phase1() {
  __shared__ int wsum[SCAN_BLK / 32];
  int tid = threadIdx.x;
  int base = blockIdx.x * SCAN_TILE + tid * SCAN_ITEMS;
  int s = 0;
#pragma unroll
  for (int j = 0; j < SCAN_ITEMS; j++) {
    int i = base + j;
    if (i < N_NODES) s += g_cnt[i];
  }
#pragma unroll
  for (int o = 16; o > 0; o >>= 1) s += __shfl_down_sync(0xffffffffu, s, o);
  if ((tid & 31) == 0) wsum[tid >> 5] = s;
  __syncthreads();
  if (tid == 0) {
    int t = 0;
#pragma unroll
    for (int w = 0; w < SCAN_BLK / 32; w++) t += wsum[w];
    g_part[blockIdx.x] = t;
  }
}

__global__ void scan_phase2() {
  if (threadIdx.x == 0) {
    int run = 0;
    for (int i = 0; i < SCAN_NBLK; i++) { int v = g_part[i]; g_part[i] = run; run += v; }
    g_rowptr[N_NODES] = run;
  }
}

__global__ __launch_bounds__(SCAN_BLK)
void scan_phase3() {
  __shared__ int wsum[SCAN_BLK / 32];
  int tid = threadIdx.x;
  int lane = tid & 31, w = tid >> 5;
  int base = blockIdx.x * SCAN_TILE + tid * SCAN_ITEMS;
  int v[SCAN_ITEMS];
  int s = 0;
#pragma unroll
  for (int j = 0; j < SCAN_ITEMS; j++) {
    int i = base + j;
    v[j] = (i < N_NODES) ? g_cnt[i] : 0;
    s += v[j];
  }
  int inc = s;
#pragma unroll
  for (int o = 1; o < 32; o <<= 1) {
    int t = __shfl_up_sync(0xffffffffu, inc, o);
    if (lane >= o) inc += t;
  }
  if (lane == 31) wsum[w] = inc;
  __syncthreads();
  if (w == 0) {
    int ws = (lane < SCAN_BLK / 32) ? wsum[lane] : 0;
#pragma unroll
    for (int o = 1; o < SCAN_BLK / 32; o <<= 1) {
      int t = __shfl_up_sync(0xffffffffu, ws, o);
      if (lane >= o) ws += t;
    }
    if (lane < SCAN_BLK / 32) wsum[lane] = ws;
  }
  __syncthreads();
  int excl = inc - s + (w > 0 ? wsum[w - 1] : 0) + g_part[blockIdx.x];
#pragma unroll
  for (int j = 0; j < SCAN_ITEMS; j++) {
    int i = base + j;
    if (i < N_NODES) { g_rowptr[i] = excl; g_cursor[i] = excl; }
    excl += v[j];
  }
}

__global__ void scatter_kernel(const int* __restrict__ src, const int* __restrict__ dst) {
  int e = blockIdx.x * blockDim.x + threadIdx.x;
  if (e >= N_EDGES) return;
  int pos = atomicAdd(&g_cursor[dst[e]], 1);
  g_csr[pos] = make_int2(src[e], e);
}

// ------------------------- gather-aggregate + combine (fused) ----------------
__global__ __launch_bounds__(256)
void aggregate_kernel(const float* __restrict__ nf, const float* __restrict__ ef,
                      const float* __restrict__ W_edge, const float* __restrict__ b_edge) {
  __shared__ float sW[EDGE_DIM][EMB];
  __shared__ float sbe[EMB];
  int tid = threadIdx.x;
  for (int i = tid; i < EDGE_DIM * EMB; i += 256) sW[i >> 7][i & 127] = W_edge[i];
  if (tid < EMB) sbe[tid] = b_edge[tid];
  __syncthreads();

  int w = tid >> 5, lane = tid & 31;
  int n = blockIdx.x * 8 + w;
  if (n >= N_NODES) return;
  int beg = g_rowptr[n], endp = g_rowptr[n + 1];
  float deg = (float)(endp - beg);

  const float4* nf4 = reinterpret_cast<const float4*>(nf);
  const float4* ef4 = reinterpret_cast<const float4*>(ef);

  float4 acc0 = make_float4(0.f, 0.f, 0.f, 0.f);
  float4 acc1 = make_float4(0.f, 0.f, 0.f, 0.f);
  float4 ea0 = make_float4(0.f, 0.f, 0.f, 0.f);
  float4 ea1 = make_float4(0.f, 0.f, 0.f, 0.f);

  int i = beg;
  for (; i + 1 < endp; i += 2) {
    int2 p0 = g_csr[i], p1 = g_csr[i + 1];
    float4 v0 = __ldg(&nf4[(size_t)p0.x * 32 + lane]);
    float4 v1 = __ldg(&nf4[(size_t)p1.x * 32 + lane]);
    acc0.x += v0.x; acc0.y += v0.y; acc0.z += v0.z; acc0.w += v0.w;
    acc1.x += v1.x; acc1.y += v1.y; acc1.z += v1.z; acc1.w += v1.w;
    if (lane < 4) {
      float4 t0 = __ldg(&ef4[(size_t)p0.y * 4 + lane]);
      float4 t1 = __ldg(&ef4[(size_t)p1.y * 4 + lane]);
      ea0.x += t0.x; ea0.y += t0.y; ea0.z += t0.z; ea0.w += t0.w;
      ea1.x += t1.x; ea1.y += t1.y; ea1.z += t1.z; ea1.w += t1.w;
    }
  }
  if (i < endp) {
    int2 p0 = g_csr[i];
    float4 v0 = __ldg(&nf4[(size_t)p0.x * 32 + lane]);
    acc0.x += v0.x; acc0.y += v0.y; acc0.z += v0.z; acc0.w += v0.w;
    if (lane < 4) {
      float4 t0 = __ldg(&ef4[(size_t)p0.y * 4 + lane]);
      ea0.x += t0.x; ea0.y += t0.y; ea0.z += t0.z; ea0.w += t0.w;
    }
  }
  float4 acc = make_float4(acc0.x + acc1.x, acc0.y + acc1.y,
                           acc0.z + acc1.z, acc0.w + acc1.w);
  float4 ea = make_float4(ea0.x + ea1.x, ea0.y + ea1.y, ea0.z + ea1.z, ea0.w + ea1.w);

  int srcl = lane >> 2, comp = lane & 3;
  float ex = __shfl_sync(0xffffffffu, ea.x, srcl);
  float ey = __shfl_sync(0xffffffffu, ea.y, srcl);
  float ez = __shfl_sync(0xffffffffu, ea.z, srcl);
  float ew = __shfl_sync(0xffffffffu, ea.w, srcl);
  float ev = (comp == 0) ? ex : (comp == 1) ? ey : (comp == 2) ? ez : ew;

  int c4 = lane * 4;
  acc.x += deg * sbe[c4 + 0];
  acc.y += deg * sbe[c4 + 1];
  acc.z += deg * sbe[c4 + 2];
  acc.w += deg * sbe[c4 + 3];
#pragma unroll
  for (int k = 0; k < EDGE_DIM; k++) {
    float s = __shfl_sync(0xffffffffu, ev, k);
    acc.x = fmaf(s, sW[k][c4 + 0], acc.x);
    acc.y = fmaf(s, sW[k][c4 + 1], acc.y);
    acc.z = fmaf(s, sW[k][c4 + 2], acc.z);
    acc.w = fmaf(s, sW[k][c4 + 3], acc.w);
  }
  fp162 h0, h1, l0, l1;
  splith(acc.x, h0.x, l0.x); splith(acc.y, h0.y, l0.y);
  splith(acc.z, h1.x, l1.x); splith(acc.w, h1.y, l1.y);
  size_t off = (size_t)n * EMB + c4;
  *reinterpret_cast<fp162*>(&g_a_hi[off]) = h0;
  *reinterpret_cast<fp162*>(&g_a_hi[off + 2]) = h1;
  *reinterpret_cast<fp162*>(&g_a_lo[off]) = l0;
  *reinterpret_cast<fp162*>(&g_a_lo[off + 2]) = l1;
}

// ------------------------- fused MLP (fp16 2-product, c1 in smem) -----------
#define A_STRIDE 48
#define B_STRIDE 144
#define A_HI_OFF 0
#define A_LO_OFF (128 * A_STRIDE)                     // 6144
#define B_OFF (2 * 128 * A_STRIDE)                    // 12288
#define STAGE_ELEMS (B_OFF + 32 * B_STRIDE)           // 16896 fp16
#define STAGE_BYTES (STAGE_ELEMS * 2)                 // 33792
#define EPI_STRIDE 132

// c1 tile in smem: 128 rows x 256 K, hi+lo fp16 planes, stride 264
#define C1_STRIDE 264
#define C1_LO (128 * C1_STRIDE)                       // 33792 elems
#define C1_ELEMS (2 * 128 * C1_STRIDE)                // 67584 elems (135168 B)
#define STG_OFF C1_ELEMS
// phase-B B-only stages (W2 single plane)
#define BST_ELEMS (32 * B_STRIDE)                     // 4608 elems / stage
#define BST_BYTES (BST_ELEMS * 2)                     // 9216
#define FUSED_SMEM_BYTES (C1_ELEMS * 2 + 2 * STAGE_BYTES)  // 202752

__global__ __launch_bounds__(256, 1)
void fused_mlp(const float* __restrict__ b1, const float* __restrict__ b2) {
  constexpr int M = N_NODES;
  extern __shared__ __align__(16) fp16 smb[];
  fp16* c1 = smb;                                      // hi at 0, lo at C1_LO
  fp16* stg = smb + STG_OFF;
  float* smf = reinterpret_cast<float*>(smb + STG_OFF);
  __shared__ float sb1[HID];
  __shared__ float sb2[EMB];
  const uint32_t stg_b = smem_u32(smb) + STG_OFF * 2;

  int tid = threadIdx.x;
  int wid = tid >> 5;
  int wm = wid & 3;
  int wn = wid >> 2;
  int bm = blockIdx.x * 128;

  if (tid < HID) sb1[tid] = b1[tid];
  if (tid < EMB) sb2[tid] = b2[tid];

  wmma::fragment<wmma::accumulator, 16, 16, 16, float> acc[2][4];

  // ===================== phase A: c1 = relu(agg @ W1 + b1) ==================
#pragma unroll
  for (int h = 0; h < 2; h++) {
    int bn = h * 128;
#pragma unroll
    for (int mt = 0; mt < 2; mt++)
#pragma unroll
      for (int nt = 0; nt < 4; nt++) wmma::fill_fragment(acc[mt][nt], 0.f);

    auto prefetchA = [&](int c, int s) {
      uint32_t base = stg_b + (uint32_t)s * STAGE_BYTES;
      int k0 = c * 32;
#pragma unroll
      for (int l = 0; l < 2; l++) {
        int u = tid + l * 256;
        int ar = u >> 2, as_ = u & 3;
        int gr = bm + ar;
        uint32_t ok = (gr < M) ? 16u : 0u;
        size_t ago = (size_t)gr * EMB + k0 + as_ * 8;
        uint32_t aso = (uint32_t)(ar * A_STRIDE + as_ * 8) * 2;
        cp16z(base + aso, &g_a_hi[ago], ok);
        cp16z(base + A_LO_OFF * 2 + aso, &g_a_lo[ago], ok);
        int br = u >> 4, bs = u & 15;
        size_t bgo = (size_t)(k0 + br) * HID + bn + bs * 8;
        uint32_t bso = (uint32_t)(br * B_STRIDE + bs * 8) * 2;
        cp16(base + B_OFF * 2 + bso, &g_w1h[bgo]);
      }
    };

    __syncthreads();   // stage/smf area free before overwriting
    prefetchA(0, 0); CP_COMMIT();
    prefetchA(1, 1); CP_COMMIT();

    for (int c = 0; c < 4; c++) {
      CP_WAIT1();
      __syncthreads();
      const fp16* st = stg + (c & 1) * STAGE_ELEMS;
#pragma unroll
      for (int ks = 0; ks < 2; ks++) {
        wmma::fragment<wmma::matrix_a, 16, 16, 16, fp16, wmma::row_major> ah[2], al[2];
#pragma unroll
        for (int mt = 0; mt < 2; mt++) {
          const fp16* ap = st + (wm * 32 + mt * 16) * A_STRIDE + ks * 16;
          wmma::load_matrix_sync(ah[mt], ap + A_HI_OFF, A_STRIDE);
          wmma::load_matrix_sync(al[mt], ap + A_LO_OFF, A_STRIDE);
        }
#pragma unroll
        for (int nt = 0; nt < 4; nt++) {
          wmma::fragment<wmma::matrix_b, 16, 16, 16, fp16, wmma::row_major> bh;
          const fp16* bp = st + B_OFF + (ks * 16) * B_STRIDE + wn * 64 + nt * 16;
          wmma::load_matrix_sync(bh, bp, B_STRIDE);
#pragma unroll
          for (int mt = 0; mt < 2; mt++) {
            wmma::mma_sync(acc[mt][nt], ah[mt], bh, acc[mt][nt]);
            wmma::mma_sync(acc[mt][nt], al[mt], bh, acc[mt][nt]);
          }
        }
      }
      __syncthreads();
      if (c + 2 < 4) prefetchA(c + 2, c & 1);
      CP_COMMIT();
    }

    // epilogue: acc -> smf -> bias/relu/split -> c1 smem planes
    CP_WAIT0();
    __syncthreads();
#pragma unroll
    for (int mt = 0; mt < 2; mt++)
#pragma unroll
      for (int nt = 0; nt < 4; nt++)
        wmma::store_matrix_sync(&smf[(wm * 32 + mt * 16) * EPI_STRIDE + wn * 64 + nt * 16],
                                acc[mt][nt], EPI_STRIDE, wmma::mem_row_major);
    __syncthreads();
    {
      int r = tid >> 1;
      int c0 = (tid & 1) * 64;
#pragma unroll
      for (int j = 0; j < 64; j += 4) {
        float4 v = *reinterpret_cast<float4*>(&smf[r * EPI_STRIDE + c0 + j]);
        v.x = fmaxf(v.x + sb1[bn + c0 + j + 0], 0.f);
        v.y = fmaxf(v.y + sb1[bn + c0 + j + 1], 0.f);
        v.z = fmaxf(v.z + sb1[bn + c0 + j + 2], 0.f);
        v.w = fmaxf(v.w + sb1[bn + c0 + j + 3], 0.f);
        fp162 h0, h1, l0, l1;
        splith(v.x, h0.x, l0.x); splith(v.y, h0.y, l0.y);
        splith(v.z, h1.x, l1.x); splith(v.w, h1.y, l1.y);
        int off = r * C1_STRIDE + bn + c0 + j;
        *reinterpret_cast<fp162*>(&c1[off]) = h0;
        *reinterpret_cast<fp162*>(&c1[off + 2]) = h1;
        *reinterpret_cast<fp162*>(&c1[C1_LO + off]) = l0;
        *reinterpret_cast<fp162*>(&c1[C1_LO + off + 2]) = l1;
      }
    }
    __syncthreads();
  }

  // ===================== phase B: h = c1 @ W2 + b2 ==========================
#pragma unroll
  for (int mt = 0; mt < 2; mt++)
#pragma unroll
    for (int nt = 0; nt < 4; nt++) wmma::fill_fragment(acc[mt][nt], 0.f);

  auto prefetchB = [&](int c, int s) {
    uint32_t base = stg_b + (uint32_t)s * BST_BYTES;
    int k0 = c * 32;
#pragma unroll
    for (int l = 0; l < 2; l++) {
      int u = tid + l * 256;
      int br = u >> 4, bs = u & 15;
      size_t bgo = (size_t)(k0 + br) * EMB + bs * 8;
      uint32_t bso = (uint32_t)(br * B_STRIDE + bs * 8) * 2;
      cp16(base + bso, &g_w2h[bgo]);
    }
  };

  prefetchB(0, 0); CP_COMMIT();
  prefetchB(1, 1); CP_COMMIT();

  for (int c = 0; c < 8; c++) {
    CP_WAIT1();
    __syncthreads();
    const fp16* bst = stg + (c & 1) * BST_ELEMS;
#pragma unroll
    for (int ks = 0; ks < 2; ks++) {
      wmma::fragment<wmma::matrix_a, 16, 16, 16, fp16, wmma::row_major> ah[2], al[2];
#pragma unroll
      for (int mt = 0; mt < 2; mt++) {
        const fp16* ap = c1 + (wm * 32 + mt * 16) * C1_STRIDE + c * 32 + ks * 16;
        wmma::load_matrix_sync(ah[mt], ap, C1_STRIDE);
        wmma::load_matrix_sync(al[mt], ap + C1_LO, C1_STRIDE);
      }
#pragma unroll
      for (int nt = 0; nt < 4; nt++) {
        wmma::fragment<wmma::matrix_b, 16, 16, 16, fp16, wmma::row_major> bh;
        const fp16* bp = bst + (ks * 16) * B_STRIDE + wn * 64 + nt * 16;
        wmma::load_matrix_sync(bh, bp, B_STRIDE);
#pragma unroll
        for (int mt = 0; mt < 2; mt++) {
          wmma::mma_sync(acc[mt][nt], ah[mt], bh, acc[mt][nt]);
          wmma::mma_sync(acc[mt][nt], al[mt], bh, acc[mt][nt]);
        }
      }
    }
    __syncthreads();
    if (c + 2 < 8) prefetchB(c + 2, c & 1);
    CP_COMMIT();
  }

  // epilogue: bias, store h, fused BN stats
  CP_WAIT0();
  __syncthreads();
#pragma unroll
  for (int mt = 0; mt < 2; mt++)
#pragma unroll
    for (int nt = 0; nt < 4; nt++)
      wmma::store_matrix_sync(&smf[(wm * 32 + mt * 16) * EPI_STRIDE + wn * 64 + nt * 16],
                              acc[mt][nt], EPI_STRIDE, wmma::mem_row_major);
  __syncthreads();
  {
    int r = tid >> 1;
    int c0 = (tid & 1) * 64;
    int gr = bm + r;
    if (gr < M) {
#pragma unroll
      for (int j = 0; j < 64; j += 4) {
        float4 v = *reinterpret_cast<float4*>(&smf[r * EPI_STRIDE + c0 + j]);
        v.x += sb2[c0 + j + 0]; v.y += sb2[c0 + j + 1];
        v.z += sb2[c0 + j + 2]; v.w += sb2[c0 + j + 3];
        *reinterpret_cast<float4*>(&g_h[(size_t)gr * EMB + c0 + j]) = v;
      }
    }
  }
  __syncthreads();
  {
    int cc = tid & 127;
    int seg = tid >> 7;
    float b = sb2[cc];
    float s = 0.f, q = 0.f;
#pragma unroll
    for (int rr = 0; rr < 64; rr++) {
      int gr = bm + seg * 64 + rr;
      if (gr < M) {
        float v = smf[(seg * 64 + rr) * EPI_STRIDE + cc] + b;
        s += v; q += v * v;
      }
    }
    atomicAdd(&g_sum[cc], s);
    atomicAdd(&g_sumsq[cc], q);
  }
}

// ------------------------- BN apply (finalize folded in) --------------------
__global__ void bn_apply(const float* __restrict__ gamma, const float* __restrict__ beta,
                         float* __restrict__ out) {
  __shared__ float ssc[EMB], ssh[EMB];
  int tid = threadIdx.x;
  if (tid < EMB) {
    const float invM = 1.0f / (float)N_NODES;
    float mean = g_sum[tid] * invM;
    float var = g_sumsq[tid] * invM - mean * mean;
    float sc = gamma[tid] * rsqrtf(var + 1e-5f);
    ssc[tid] = sc;
    ssh[tid] = beta[tid] - mean * sc;
  }
  __syncthreads();
  int i = blockIdx.x * blockDim.x + tid;
  const int total4 = N_NODES * EMB / 4;
  if (i >= total4) return;
  int c = (i & 31) << 2;
  float4 h = reinterpret_cast<const float4*>(g_h)[i];
  float4 o;
  o.x = h.x * ssc[c + 0] + ssh[c + 0];
  o.y = h.y * ssc[c + 1] + ssh[c + 1];
  o.z = h.z * ssc[c + 2] + ssh[c + 2];
  o.w = h.w * ssc[c + 3] + ssh[c + 3];
  reinterpret_cast<float4*>(out)[i] = o;
}

// ------------------------- launch -------------------------------------------
extern "C" void kernel_launch(void* const* d_in, const int* in_sizes, int n_in,
                              void* d_out, int out_size) {
  const float* node_feats = (const float*)d_in[0];
  const float* edge_feats = (const float*)d_in[1];
  const float* W_edge     = (const float*)d_in[2];
  const float* b_edge     = (const float*)d_in[3];
  const float* W1         = (const float*)d_in[4];
  const float* b1         = (const float*)d_in[5];
  const float* W2         = (const float*)d_in[6];
  const float* b2         = (const float*)d_in[7];
  const float* bn_gamma   = (const float*)d_in[8];
  const float* bn_beta    = (const float*)d_in[9];
  const int*   src        = (const int*)d_in[10];
  const int*   dst        = (const int*)d_in[11];
  float* out = (float*)d_out;

  cudaFuncSetAttribute(fused_mlp,
                       cudaFuncAttributeMaxDynamicSharedMemorySize, FUSED_SMEM_BYTES);

  const int MTILES = (N_NODES + 127) / 128;  // 391

  init_kernel<<<(N_NODES + 255) / 256, 256>>>(W1, W2);
  hist_kernel<<<(N_EDGES + 255) / 256, 256>>>(dst);
  scan_phase1<<<SCAN_NBLK, SCAN_BLK>>>();
  scan_phase2<<<1, 32>>>();
  scan_phase3<<<SCAN_NBLK, SCAN_BLK>>>();
  scatter_kernel<<<(N_EDGES + 255) / 256, 256>>>(src, dst);
  aggregate_kernel<<<(N_NODES + 7) / 8, 256>>>(node_feats, edge_feats, W_edge, b_edge);
  fused_mlp<<<MTILES, 256, FUSED_SMEM_BYTES>>>(b1, b2);
  bn_apply<<<(N_NODES * EMB / 4 + 255) / 256, 256>>>(bn_gamma, bn_beta, out);
}